// round 12
// baseline (speedup 1.0000x reference)
#include <cuda_runtime.h>
#include <math_constants.h>

// Problem shape (fixed by the benchmark)
#define BB   16
#define KC   5
#define NP   4096
#define DD   1024
#define KNN  9

#define BLK_X 32               // producer (sims) blocks per batch
#define GRID_X (BLK_X + KC)    // + 5 consumer (gather) blocks per batch = 37
#define RPG   2                // rows per unit
#define UPW   8                // units per warp (8 warps * 8 units * 2 rows = 128 rows)
#define ROWS_PER_BLK 128
#define NCAND (BLK_X * KNN)    // 288 candidates per (b,k)

// -------- scratch (no device allocation allowed -> __device__ globals) ------
__device__ float2   g_cand[BB * KC * NCAND];  // (val, idx-as-float-bits) 184 KB
__device__ float    g_invnorm[BB * NP];       // 1/||patch||             256 KB
__device__ unsigned g_count[BB];              // arrival counters (0-init; reset in-kernel)

// ============================================================================
// Fused kernel. grid (37,16), 256 threads, one wave.
//  bx <  32: producer — R7-proven streaming pass over its 128 patch rows
//            (268 MB total -> memory bound) + block-local top-9 per cue ->
//            g_cand, then release-fence + count.
//  bx >= 32: consumer for cue k = bx-32 — poll until all 32 producers of its
//            batch arrived, then merge 288 candidates -> top-9 -> gather the
//            output row. Merge+gather overlap with other batches' producers.
// Cue used RAW (positive row-scalar -> identical top-9 set; output involves
// only normalized patches).
// ============================================================================
__global__ void __launch_bounds__(256, 4) fused_kernel(const float* __restrict__ patches,
                                                       const float* __restrict__ cue,
                                                       float* __restrict__ out) {
    const int b = blockIdx.y;
    const int bx = blockIdx.x;

    __shared__ float4 s_cue[KC * DD / 4];        // 20 KB (producer: raw cue)
    __shared__ float  s_s[KC][ROWS_PER_BLK];     // 2.5 KB block-local cosines
    __shared__ float  s_v[NCAND];                // consumer: candidate values
    __shared__ int    s_i[NCAND];                // consumer: candidate indices
    __shared__ int    s_top[KNN];
    __shared__ float  s_inv[KNN];

    const int warp = threadIdx.x >> 5;
    const int lane = threadIdx.x & 31;
    const int tid  = threadIdx.x;

    if (bx >= BLK_X) {
        // ==================== CONSUMER PATH ====================
        const int k  = bx - BLK_X;              // cue 0..4
        const int bk = b * KC + k;

        // wait for all 32 producers of this batch
        if (tid == 0) {
            while (*(volatile unsigned*)&g_count[b] < BLK_X) __nanosleep(200);
        }
        __syncthreads();
        __threadfence();                        // acquire producers' writes

        const float2* cand = g_cand + (size_t)bk * NCAND;
        for (int t = tid; t < NCAND; t += 256) {
            const float2 c = cand[t];
            s_v[t] = c.x;
            s_i[t] = __float_as_int(c.y);
        }
        __syncthreads();

        if (tid < 32) {
            // lane holds slots lane + s*32, s = 0..8 (register resident)
            float v[9]; int x[9];
            #pragma unroll
            for (int s = 0; s < 9; s++) {
                const int g = lane + s * 32;
                v[s] = s_v[g]; x[s] = s_i[g];
            }
            for (int it = 0; it < KNN; it++) {
                float bv = -CUDART_INF_F; int bi = NP; int bs = 0;
                #pragma unroll
                for (int s = 0; s < 9; s++)
                    if (v[s] > bv || (v[s] == bv && x[s] < bi)) { bv = v[s]; bi = x[s]; bs = s; }
                int blane = lane;
                #pragma unroll
                for (int o = 16; o; o >>= 1) {
                    const float ov = __shfl_xor_sync(0xffffffffu, bv, o);
                    const int   oi = __shfl_xor_sync(0xffffffffu, bi, o);
                    const int   os = __shfl_xor_sync(0xffffffffu, bs, o);
                    const int   ol = __shfl_xor_sync(0xffffffffu, blane, o);
                    if (ov > bv || (ov == bv && oi < bi)) { bv = ov; bi = oi; bs = os; blane = ol; }
                }
                if (lane == blane) v[bs] = -CUDART_INF_F;        // mask winner
                if (lane == 0) s_top[it] = bi;
            }
            if (lane < KNN)
                s_inv[lane] = g_invnorm[(size_t)b * NP + s_top[lane]] * (1.0f / (float)KNN);
        }
        __syncthreads();

        // gather: each thread owns one float4 of the D=1024 output
        float4 acc = make_float4(0.f, 0.f, 0.f, 0.f);
        #pragma unroll
        for (int i = 0; i < KNN; i++) {
            const float4 v = ((const float4*)(patches +
                              ((size_t)b * NP + s_top[i]) * DD))[tid];
            const float sc = s_inv[i];
            acc.x = fmaf(v.x, sc, acc.x);
            acc.y = fmaf(v.y, sc, acc.y);
            acc.z = fmaf(v.z, sc, acc.z);
            acc.w = fmaf(v.w, sc, acc.w);
        }
        ((float4*)out)[(size_t)bk * (DD / 4) + tid] = acc;

        // arrival + reset for graph-replay determinism (37th arrival resets)
        __syncthreads();
        if (tid == 0) {
            __threadfence();
            const unsigned old = atomicAdd(&g_count[b], 1u);
            if (old == GRID_X - 1) {            // last of 37 -> reset
                __threadfence();
                *(volatile unsigned*)&g_count[b] = 0u;
            }
        }
        return;
    }

    // ==================== PRODUCER PATH (R7 sims, unchanged) ====================
    {
        const float4* src = (const float4*)(cue + (size_t)b * KC * DD);
        for (int i = tid; i < KC * DD / 4; i += 256) s_cue[i] = src[i];
    }
    __syncthreads();

    const float4* pbase = (const float4*)(patches + (size_t)b * NP * DD);
    const int u0 = bx * (ROWS_PER_BLK / RPG);    // first unit of this block

    const float4* p = pbase + (size_t)(u0 + warp) * RPG * (DD / 4);
    float4 v0[RPG], v1[RPG], v2[RPG];
    #pragma unroll
    for (int rr = 0; rr < RPG; rr++) {
        v0[rr] = __ldcs(&p[lane + rr * (DD / 4)]);
        v1[rr] = __ldcs(&p[lane + 32 + rr * (DD / 4)]);
    }

    for (int m = 0; m < UPW; m++) {
        const bool has_next = (m < UPW - 1);
        const float4* pn = p + 8 * RPG * (DD / 4);    // next unit (stride 8)

        float acc[RPG][6];
        #pragma unroll
        for (int rr = 0; rr < RPG; rr++)
            #pragma unroll
            for (int i = 0; i < 6; i++) acc[rr][i] = 0.f;

        #pragma unroll
        for (int j = 0; j < 8; j++) {
            if (j < 6) {
                const int offn = lane + (j + 2) * 32;
                #pragma unroll
                for (int rr = 0; rr < RPG; rr++)
                    v2[rr] = __ldcs(&p[offn + rr * (DD / 4)]);
            } else if (has_next) {
                const int offn = lane + (j - 6) * 32;
                #pragma unroll
                for (int rr = 0; rr < RPG; rr++)
                    v2[rr] = __ldcs(&pn[offn + rr * (DD / 4)]);
            }

            const int off = lane + j * 32;
            #pragma unroll
            for (int rr = 0; rr < RPG; rr++) {
                acc[rr][5] = fmaf(v0[rr].x, v0[rr].x, acc[rr][5]);
                acc[rr][5] = fmaf(v0[rr].y, v0[rr].y, acc[rr][5]);
                acc[rr][5] = fmaf(v0[rr].z, v0[rr].z, acc[rr][5]);
                acc[rr][5] = fmaf(v0[rr].w, v0[rr].w, acc[rr][5]);
            }
            #pragma unroll
            for (int k = 0; k < KC; k++) {
                const float4 c = s_cue[k * (DD / 4) + off];
                #pragma unroll
                for (int rr = 0; rr < RPG; rr++) {
                    acc[rr][k] = fmaf(v0[rr].x, c.x, acc[rr][k]);
                    acc[rr][k] = fmaf(v0[rr].y, c.y, acc[rr][k]);
                    acc[rr][k] = fmaf(v0[rr].z, c.z, acc[rr][k]);
                    acc[rr][k] = fmaf(v0[rr].w, c.w, acc[rr][k]);
                }
            }
            #pragma unroll
            for (int rr = 0; rr < RPG; rr++) { v0[rr] = v1[rr]; v1[rr] = v2[rr]; }
        }

        const int lrow0 = (warp + m * 8) * RPG;
        #pragma unroll
        for (int rr = 0; rr < RPG; rr++) {
            #pragma unroll
            for (int i = 0; i < 6; i++)
                #pragma unroll
                for (int o = 16; o; o >>= 1)
                    acc[rr][i] += __shfl_xor_sync(0xffffffffu, acc[rr][i], o);
            const float inv = rsqrtf(fmaxf(acc[rr][5], 1e-24f));
            float val = acc[rr][0];
            if (lane == 1) val = acc[rr][1];
            if (lane == 2) val = acc[rr][2];
            if (lane == 3) val = acc[rr][3];
            if (lane == 4) val = acc[rr][4];
            if (lane < 5)
                s_s[lane][lrow0 + rr] = val * inv;
            else if (lane == 5)
                g_invnorm[(size_t)b * NP + bx * ROWS_PER_BLK + lrow0 + rr] = inv;
        }

        if (has_next) p = pn;
    }
    __syncthreads();

    // Block-local top-9 per cue: warp k selects from s_s[k][0..128).
    if (warp < KC) {
        const int k = warp;
        float v4[4];
        const int base = lane * 4;
        #pragma unroll
        for (int i = 0; i < 4; i++) v4[i] = s_s[k][base + i];

        float2* cand = g_cand + ((size_t)(b * KC + k) * BLK_X + bx) * KNN;
        for (int it = 0; it < KNN; it++) {
            float bv = -CUDART_INF_F; int bi = ROWS_PER_BLK;
            #pragma unroll
            for (int i = 0; i < 4; i++)
                if (v4[i] > bv) { bv = v4[i]; bi = base + i; }   // lowest idx on tie
            #pragma unroll
            for (int o = 16; o; o >>= 1) {
                const float ov = __shfl_xor_sync(0xffffffffu, bv, o);
                const int   oi = __shfl_xor_sync(0xffffffffu, bi, o);
                if (ov > bv || (ov == bv && oi < bi)) { bv = ov; bi = oi; }
            }
            if ((bi >> 2) == lane) v4[bi & 3] = -CUDART_INF_F;   // mask winner
            if (lane == 0)
                cand[it] = make_float2(bv, __int_as_float(bx * ROWS_PER_BLK + bi));
        }
    }

    // release our cand/invnorm writes, then signal arrival
    __syncthreads();
    __threadfence();
    if (tid == 0) atomicAdd(&g_count[b], 1u);
}

// ============================================================================
extern "C" void kernel_launch(void* const* d_in, const int* in_sizes, int n_in,
                              void* d_out, int out_size) {
    const float* cue     = (const float*)d_in[0];
    const float* patches = (const float*)d_in[1];
    // defensive: identify by element count (cue = 81920, patches = 67108864)
    if (n_in >= 2 && in_sizes[0] > in_sizes[1]) {
        cue     = (const float*)d_in[1];
        patches = (const float*)d_in[0];
    }

    dim3 g1(GRID_X, BB);
    fused_kernel<<<g1, 256>>>(patches, cue, (float*)d_out);
}